// round 9
// baseline (speedup 1.0000x reference)
#include <cuda_runtime.h>
#include <math.h>

#define BVOL  (128*128*128)
#define VOL   (2*BVOL)          // 4,194,304
#define PLANE (128*128)
#define FVOL  (2*3*BVOL)        // 12,582,912

#define NLCC 1760               // 5x11 xy-tiles * 8 z-segs * 2 pairs * 2 batches
#define NREG 292
#define NTV  84
#define NTOT (NLCC + NREG + 2*NTV)   // 2220 = 5 waves at 3 CTAs/SM

__device__ double g_acc[12];    // zero-init; finalizer re-zeros each launch
__device__ unsigned int g_done;
// 0 reg | 1 gg0 2 pp0 3 gp0 | 4 gg1 5 pp1 6 gp1 | 7 tvgp0 8 tvsum0 | 9 tvgp1 10 tvsum1

__device__ __forceinline__ float warpSum(float v) {
#pragma unroll
    for (int o = 16; o; o >>= 1) v += __shfl_down_sync(0xffffffffu, v, o);
    return v;
}

__device__ __forceinline__ double accRead(int i) {
    return atomicAdd(&g_acc[i], 0.0);
}

__global__ void __launch_bounds__(512, 3)
fused_main(const float* __restrict__ F0,  const float* __restrict__ F0g,
           const float* __restrict__ I0,  const float* __restrict__ I0R,
           const float* __restrict__ I1,  const float* __restrict__ I1R,
           const float* __restrict__ S0,  const float* __restrict__ S0g,
           const float* __restrict__ S1,  const float* __restrict__ S1g,
           float* __restrict__ out) {
    __shared__ float2 smA[2][16][32];   // z-sum plane for even z of the pair
    __shared__ float2 smB[2][16][32];   // z-sum plane for odd z of the pair
    __shared__ float red[5][16];

    const int tx  = threadIdx.x;          // warp = x-row
    const int ty  = threadIdx.y;          // 0..15
    const int lin = ty * 32 + tx;
    const int lane = lin & 31, wid = lin >> 5;
    const int bid = blockIdx.x;

    if (bid < NLCC) {
        // ---------------- fully fused LCC, 2 z-planes per barrier ----------
        int t = bid;
        int pb   = t & 3;  t >>= 2;      // pair*2 + batch
        int zseg = t & 7;  t >>= 3;      // 8 z-segments of 16
        int tyid = t % 11;               // 11 y-tiles of 12
        int txid = t / 11;               // 5 x-tiles of 28
        int pair = pb >> 1, n = pb & 1;
        const float* __restrict__ gt = pair ? I1  : I0;
        const float* __restrict__ pr = pair ? I1R : I0R;
        const int accBase = 1 + 3 * pair;

        const int x0 = txid * 28, y0 = tyid * 12, z0 = zseg * 16;
        const int gx = x0 + tx - 2, gy = y0 + ty - 2;
        const bool colValid = (gx >= 0) && (gx < 128) && (gy >= 0) && (gy < 128);
        const bool inter = (tx >= 2) && (tx < 30) && (ty >= 2) && (ty < 14) &&
                           (gx < 128) && (gy < 128);
        const int cbase = n * BVOL + gy * 128 + gx;

        // window g0..g3 = planes z0-2 .. z0+1
        float g0 = 0.f, g1 = 0.f, g2 = 0.f, g3 = 0.f;
        float p0 = 0.f, p1 = 0.f, p2 = 0.f, p3 = 0.f;
        if (colValid) {
            if (z0 >= 2) { g0 = gt[cbase + (z0-2) * PLANE]; p0 = pr[cbase + (z0-2) * PLANE]; }
            if (z0 >= 1) { g1 = gt[cbase + (z0-1) * PLANE]; p1 = pr[cbase + (z0-1) * PLANE]; }
            g2 = gt[cbase + z0 * PLANE];       p2 = pr[cbase + z0 * PLANE];
            g3 = gt[cbase + (z0+1) * PLANE];   p3 = pr[cbase + (z0+1) * PLANE];
        }

        float agg = 0.f, app = 0.f, agp = 0.f;

#pragma unroll 2
        for (int zi = 0; zi < 16; zi += 2) {
            const int buf = (zi >> 1) & 1;
            const int za = z0 + zi + 2;       // incoming plane for out z=zi
            const int zb = z0 + zi + 3;       // incoming plane for out z=zi+1
            float nga = 0.f, npa = 0.f, ngb = 0.f, npb = 0.f;
            if (colValid) {
                if (za < 128) { nga = gt[cbase + za * PLANE]; npa = pr[cbase + za * PLANE]; }
                if (zb < 128) { ngb = gt[cbase + zb * PLANE]; npb = pr[cbase + zb * PLANE]; }
            }
            // z-sums for the two output planes
            smA[buf][ty][tx] = make_float2(((g0 + g1) + (g2 + g3)) + nga,
                                           ((p0 + p1) + (p2 + p3)) + npa);
            smB[buf][ty][tx] = make_float2(((g1 + g2) + (g3 + nga)) + ngb,
                                           ((p1 + p2) + (p3 + npa)) + npb);
            __syncthreads();

            float yaG = 0.f, yaP = 0.f, ybG = 0.f, ybP = 0.f;
            if (ty >= 2 && ty < 14) {
                float2 a0 = smA[buf][ty-2][tx], a1 = smA[buf][ty-1][tx];
                float2 a2 = smA[buf][ty  ][tx], a3 = smA[buf][ty+1][tx];
                float2 a4 = smA[buf][ty+2][tx];
                yaG = ((a0.x + a1.x) + (a2.x + a3.x)) + a4.x;
                yaP = ((a0.y + a1.y) + (a2.y + a3.y)) + a4.y;
                float2 b0 = smB[buf][ty-2][tx], b1 = smB[buf][ty-1][tx];
                float2 b2 = smB[buf][ty  ][tx], b3 = smB[buf][ty+1][tx];
                float2 b4 = smB[buf][ty+2][tx];
                ybG = ((b0.x + b1.x) + (b2.x + b3.x)) + b4.x;
                ybP = ((b0.y + b1.y) + (b2.y + b3.y)) + b4.y;
            }
            // x-conv via shuffles, both planes
            float am2G = __shfl_up_sync(0xffffffffu, yaG, 2);
            float am1G = __shfl_up_sync(0xffffffffu, yaG, 1);
            float ap1G = __shfl_down_sync(0xffffffffu, yaG, 1);
            float ap2G = __shfl_down_sync(0xffffffffu, yaG, 2);
            float am2P = __shfl_up_sync(0xffffffffu, yaP, 2);
            float am1P = __shfl_up_sync(0xffffffffu, yaP, 1);
            float ap1P = __shfl_down_sync(0xffffffffu, yaP, 1);
            float ap2P = __shfl_down_sync(0xffffffffu, yaP, 2);
            float bm2G = __shfl_up_sync(0xffffffffu, ybG, 2);
            float bm1G = __shfl_up_sync(0xffffffffu, ybG, 1);
            float bp1G = __shfl_down_sync(0xffffffffu, ybG, 1);
            float bp2G = __shfl_down_sync(0xffffffffu, ybG, 2);
            float bm2P = __shfl_up_sync(0xffffffffu, ybP, 2);
            float bm1P = __shfl_up_sync(0xffffffffu, ybP, 1);
            float bp1P = __shfl_down_sync(0xffffffffu, ybP, 1);
            float bp2P = __shfl_down_sync(0xffffffffu, ybP, 2);
            if (inter) {
                float mgA = (((am2G + am1G) + (yaG + ap1G)) + ap2G) * 0.008f;
                float mpA = (((am2P + am1P) + (yaP + ap1P)) + ap2P) * 0.008f;
                float dgA = g2 - mgA;            // center z=zi is plane g2
                float dpA = p2 - mpA;
                agg = fmaf(dgA, dgA, agg);
                app = fmaf(dpA, dpA, app);
                agp = fmaf(dgA, dpA, agp);

                float mgB = (((bm2G + bm1G) + (ybG + bp1G)) + bp2G) * 0.008f;
                float mpB = (((bm2P + bm1P) + (ybP + bp1P)) + bp2P) * 0.008f;
                float dgB = g3 - mgB;            // center z=zi+1 is plane g3
                float dpB = p3 - mpB;
                agg = fmaf(dgB, dgB, agg);
                app = fmaf(dpB, dpB, app);
                agp = fmaf(dgB, dpB, agp);
            }
            // slide window by 2 (no trailing sync: next iter uses other buffer)
            g0 = g2; g1 = g3; g2 = nga; g3 = ngb;
            p0 = p2; p1 = p3; p2 = npa; p3 = npb;
        }

        agg = warpSum(agg); app = warpSum(app); agp = warpSum(agp);
        if (lane == 0) { red[0][wid] = agg; red[1][wid] = app; red[2][wid] = agp; }
        __syncthreads();
        if (wid == 0) {
            float a = (lane < 16) ? red[0][lane] : 0.f;
            float b = (lane < 16) ? red[1][lane] : 0.f;
            float c = (lane < 16) ? red[2][lane] : 0.f;
            a = warpSum(a); b = warpSum(b); c = warpSum(c);
            if (lane == 0) {
                atomicAdd(&g_acc[accBase + 0], (double)a);
                atomicAdd(&g_acc[accBase + 1], (double)b);
                atomicAdd(&g_acc[accBase + 2], (double)c);
            }
        }
    } else if (bid < NLCC + NREG) {
        // ---------------- reg_field: branch-free stream ----------------
        const int R = FVOL / 4;
        const int stride = NREG * 512;
        float s = 0.f;
        const float4* __restrict__ a4 = (const float4*)F0;
        const float4* __restrict__ b4 = (const float4*)F0g;
#pragma unroll 4
        for (int i = (bid - NLCC) * 512 + lin; i < R; i += stride) {
            float4 a = a4[i], b = b4[i];
            float d0 = a.x - b.x, d1 = a.y - b.y, d2 = a.z - b.z, d3 = a.w - b.w;
            s += (d0 * d0 + d1 * d1) + (d2 * d2 + d3 * d3);
        }
        s = warpSum(s);
        if (lane == 0) red[0][wid] = s;
        __syncthreads();
        if (wid == 0) {
            float v = (lane < 16) ? red[0][lane] : 0.f;
            v = warpSum(v);
            if (lane == 0) atomicAdd(&g_acc[0], (double)v);
        }
    } else {
        // ---------------- tversky ----------------
        const int which = (bid - NLCC - NREG) / NTV;
        const int rb    = (bid - NLCC - NREG) % NTV;
        const float4* __restrict__ g4 = (const float4*)(which ? S1  : S0);
        const float4* __restrict__ p4 = (const float4*)(which ? S1g : S0g);
        const int accBase = 7 + 2 * which;
        const int T = VOL / 4;
        const int stride = NTV * 512;
        float sgp = 0.f, ssm = 0.f;
#pragma unroll 4
        for (int i = rb * 512 + lin; i < T; i += stride) {
            float4 a = g4[i], b = p4[i];
            sgp += (a.x * b.x + a.y * b.y) + (a.z * b.z + a.w * b.w);
            ssm += ((a.x + b.x) + (a.y + b.y)) + ((a.z + b.z) + (a.w + b.w));
        }
        sgp = warpSum(sgp); ssm = warpSum(ssm);
        if (lane == 0) { red[0][wid] = sgp; red[1][wid] = ssm; }
        __syncthreads();
        if (wid == 0) {
            float a = (lane < 16) ? red[0][lane] : 0.f;
            float b = (lane < 16) ? red[1][lane] : 0.f;
            a = warpSum(a); b = warpSum(b);
            if (lane == 0) {
                atomicAdd(&g_acc[accBase + 0], (double)a);
                atomicAdd(&g_acc[accBase + 1], (double)b);
            }
        }
    }

    // -------- last-block finalize ----------------------------------------
    if (lin == 0) {
        __threadfence();
        unsigned int old = atomicAdd(&g_done, 1u);
        if (old == NTOT - 1) {
            double a0 = accRead(0), a1 = accRead(1), a2 = accRead(2), a3 = accRead(3);
            double a4 = accRead(4), a5 = accRead(5), a6 = accRead(6), a7 = accRead(7);
            double a8 = accRead(8), a9 = accRead(9), a10 = accRead(10);

            double reg = sqrt(a0) / (double)FVOL;
            double den0 = a1 * a2; if (den0 < 1e-5) den0 = 1e-5;
            double lcc0 = -((a3 * a3) / den0) / (double)VOL;
            double den1 = a4 * a5; if (den1 < 1e-5) den1 = 1e-5;
            double lcc1 = -((a6 * a6) / den1) / (double)VOL;
            double ds0 = a8;  if (ds0 < 1e-5) ds0 = 1e-5;
            double tv0 = -a7 / ds0;
            double ds1 = a10; if (ds1 < 1e-5) ds1 = 1e-5;
            double tv1 = -a9 / ds1;

            out[0] = (float)(reg + 10.0 * (lcc0 + lcc1) + 10.0 * (tv0 + tv1));

#pragma unroll
            for (int k = 0; k < 12; k++) g_acc[k] = 0.0;
            __threadfence();
            g_done = 0u;
        }
    }
}

extern "C" void kernel_launch(void* const* d_in, const int* in_sizes, int n_in,
                              void* d_out, int out_size) {
    const float* F0  = (const float*)d_in[0];
    const float* F0g = (const float*)d_in[1];
    const float* I0  = (const float*)d_in[2];
    const float* I0R = (const float*)d_in[3];
    const float* I1  = (const float*)d_in[4];
    const float* I1R = (const float*)d_in[5];
    const float* S0  = (const float*)d_in[6];
    const float* S0g = (const float*)d_in[7];
    const float* S1  = (const float*)d_in[8];
    const float* S1g = (const float*)d_in[9];
    float* out = (float*)d_out;

    dim3 blk(32, 16);
    fused_main<<<NTOT, blk>>>(F0, F0g, I0, I0R, I1, I1R, S0, S0g, S1, S1g, out);
}